// round 14
// baseline (speedup 1.0000x reference)
#include <cuda_runtime.h>
#include <cuda_fp16.h>
#include <math.h>

#define LNUM 4
#define DM   256
#define NH   8
#define DHH  32
#define DI   1024
#define SEG  1024
#define MEML 1024
#define KL   2048
#define BSZ  2
#define NLD  12
#define H3   768          // 3*H*DH
#define PRED_N (BSZ*NLD*SEG)
#define CORE_N (SEG*BSZ*DM)
#define SCALE 0.17677669529663687f   // 1/sqrt(32)

// ---------------- scratch (static device globals; no runtime allocation) ----------------
__device__ float  g_core   [CORE_N];
__device__ __half g_core_h [CORE_N];
__device__ __half g_heads_h[KL*BSZ*H3];              // qkv heads, fp16
__device__ __half g_r_h    [KL*DM];
__device__ __half g_rk_h   [LNUM*KL*DM];             // all layers, fp16
__device__ float  g_vec    [CORE_N];
__device__ __half g_mid_h  [SEG*BSZ*DI];
__device__ __half g_AC     [(size_t)BSZ*NH*SEG*KL];  // AC scores / probs (in-place, fp16)
__device__ __half g_BDs    [(size_t)BSZ*NH*SEG*KL];  // SHIFTED BD (fp16)
__device__ __half g_pvp    [4*CORE_N];               // PV split-K partials (fp16)
// transposed fp16 weights, [N][K] layout
__device__ __half g_wqkv_h [LNUM*H3*DM];
__device__ __half g_wrnet_h[LNUM*DM*DM];
__device__ __half g_wo_h   [LNUM*DM*DM];
__device__ __half g_wff1_h [LNUM*DI*DM];
__device__ __half g_wff2_h [LNUM*DM*DI];
__device__ __half g_mems_h [LNUM*MEML*BSZ*DM];

// ---------------- mma helpers ----------------
__device__ __forceinline__ void mma_f16(float& c0, float& c1, float& c2, float& c3,
                                        unsigned a0, unsigned a1, unsigned a2, unsigned a3,
                                        unsigned b0, unsigned b1) {
    asm volatile(
        "mma.sync.aligned.m16n8k16.row.col.f32.f16.f16.f32 "
        "{%0,%1,%2,%3},{%4,%5,%6,%7},{%8,%9},{%0,%1,%2,%3};\n"
        : "+f"(c0), "+f"(c1), "+f"(c2), "+f"(c3)
        : "r"(a0), "r"(a1), "r"(a2), "r"(a3), "r"(b0), "r"(b1));
}
__device__ __forceinline__ void cp16(void* smem_dst, const void* gsrc) {
    unsigned dst = (unsigned)__cvta_generic_to_shared(smem_dst);
    asm volatile("cp.async.ca.shared.global [%0], [%1], 16;\n" :: "r"(dst), "l"(gsrc));
}

// ---------------- batched weight prep: all 5 W[K][N] fp32 -> Wt[N][K] fp16 ----------------
// block table: qkv 768 | rnet 256 | o 256 | ff1 1024 | ff2 1024  (total 3328)
__global__ void k_transp_all(const float* __restrict__ qkv, const float* __restrict__ rnet,
                             const float* __restrict__ ow, const float* __restrict__ f1,
                             const float* __restrict__ f2) {
    __shared__ float tile[32][33];
    int bid = blockIdx.x;
    const float* W; __half* Wt; int K, N;
    if (bid < 768)       {            W = qkv;  Wt = g_wqkv_h;  K = DM; N = H3; }
    else if (bid < 1024) { bid -= 768;  W = rnet; Wt = g_wrnet_h; K = DM; N = DM; }
    else if (bid < 1280) { bid -= 1024; W = ow;   Wt = g_wo_h;    K = DM; N = DM; }
    else if (bid < 2304) { bid -= 1280; W = f1;   Wt = g_wff1_h;  K = DM; N = DI; }
    else                 { bid -= 2304; W = f2;   Wt = g_wff2_h;  K = DI; N = DM; }
    int nb = N / 32, kb = K / 32;
    int z = bid / (nb * kb);
    int rem = bid % (nb * kb);
    int ky = rem / nb, nx = rem % nb;
    W  += (size_t)z * K * N;
    Wt += (size_t)z * K * N;
    int n0 = nx * 32, k0 = ky * 32;
    int tx = threadIdx.x, ty = threadIdx.y;   // 32 x 8
    for (int r = ty; r < 32; r += 8)
        tile[r][tx] = W[(size_t)(k0 + r) * N + n0 + tx];
    __syncthreads();
    for (int r = ty; r < 32; r += 8)
        Wt[(size_t)(n0 + r) * K + k0 + tx] = __float2half_rn(tile[tx][r]);
}

// ---------------- fp32 -> fp16 elementwise ----------------
__global__ void k_cvt(const float* __restrict__ in, __half* __restrict__ out, int n) {
    int i = (blockIdx.x * blockDim.x + threadIdx.x) * 4;
    if (i >= n) return;
    float4 v = *(const float4*)(in + i);
    __half2* o = (__half2*)(out + i);
    o[0] = __floats2half2_rn(v.x, v.y);
    o[1] = __floats2half2_rn(v.z, v.w);
}

// ---------------- zero the never-written shifted-BD diagonal (j = i + 1025) ----------------
__global__ void k_zdiag() {
    int idx = blockIdx.x * blockDim.x + threadIdx.x;
    int bh = idx >> 10, i = idx & 1023;
    if (bh >= BSZ*NH || i > 1022) return;
    g_BDs[((size_t)bh * SEG + i) * KL + i + 1025] = __float2half_rn(0.f);
}

// ---------------- input projection ----------------
__global__ void k_input_proj(const float* __restrict__ src, const float* __restrict__ W_in,
                             const float* __restrict__ b_in, float* __restrict__ memout) {
    int idx = blockIdx.x * blockDim.x + threadIdx.x;
    if (idx >= CORE_N) return;
    int d  = idx & (DM - 1);
    int sb = idx >> 8;
    int b  = sb & 1;
    int s  = sb >> 1;
    float acc = b_in[d];
#pragma unroll
    for (int l = 0; l < NLD; l++)
        acc += src[((size_t)b * NLD + l) * SEG + s] * W_in[l * DM + d];
    g_core[idx] = acc;
    g_core_h[idx] = __float2half_rn(acc);
    memout[idx] = acc;   // new_mems[0] == hids[0]
}

// ---------------- positional embedding r[KLEN, D] (fp16) ----------------
__global__ void k_pos() {
    int idx = blockIdx.x * blockDim.x + threadIdx.x;
    if (idx >= KL * DM) return;
    int d = idx & (DM - 1);
    int j = idx >> 8;
    float pos = (float)(KL - 1 - j);
    int f = (d < 128) ? d : d - 128;
    float inv = powf(10000.f, -(float)f / 128.f);
    float v = pos * inv;
    g_r_h[idx] = __float2half_rn((d < 128) ? sinf(v) : cosf(v));
}

// ---------------- fp16 GEMM, cp.async 2-stage, BK=32 ----------------
// BM in {128,64}, BN=64, 256 threads (8 warps: 4(M) x 2(N)).
// Bh is [N][K] fp16 (pre-transposed). amode: 0 normal Ah, 100 cat(memsh, g_core_h),
// 101 A = sum of 4 fp16 PV partials (converted at stage).
// Output: Cf fp32 or Chh fp16 (one non-null). blockIdx.z batches B/C by strides.
template<int BM>
__global__ void __launch_bounds__(256) k_gemm_f16(
        const __half* __restrict__ Ah, int amode, const __half* __restrict__ memsh,
        const __half* __restrict__ Bh, float* Cf, __half* Chh,
        int M, int N, int K,
        const float* __restrict__ bias, int relu,
        size_t bstride, size_t cstride) {
    constexpr int MT = BM / 64;
    Bh += (size_t)blockIdx.z * bstride;
    if (Cf)  Cf  += (size_t)blockIdx.z * cstride;
    if (Chh) Chh += (size_t)blockIdx.z * cstride;
    __shared__ __half As[2][BM][40];
    __shared__ __half Bs[2][64][40];
    int t = threadIdx.x;
    int m0 = blockIdx.y * BM, n0 = blockIdx.x * 64;
    int lane = t & 31, g = lane >> 2, tg = lane & 3;
    int w = t >> 5;
    int wm = (w >> 1) * 16 * MT, wn = (w & 1) * 32;

    float c[MT][4][4];
#pragma unroll
    for (int i = 0; i < MT; i++)
#pragma unroll
        for (int j = 0; j < 4; j++)
#pragma unroll
            for (int q = 0; q < 4; q++) c[i][j][q] = 0.f;

    auto stage = [&](int k0, int s) {
#pragma unroll
        for (int i = 0; i < MT; i++) {
            int f = t + i * 256;
            int r = f >> 2, c8 = (f & 3) * 8;
            int rg = m0 + r;
            if (amode == 101) {
                size_t off = (size_t)rg * K + k0 + c8;
                float acc[8] = {0,0,0,0,0,0,0,0};
#pragma unroll
                for (int p = 0; p < 4; p++) {
                    float4 raw = *(const float4*)(g_pvp + (size_t)p * CORE_N + off);
                    const __half2* hp = (const __half2*)&raw;
#pragma unroll
                    for (int q = 0; q < 4; q++) {
                        float2 fv = __half22float2(hp[q]);
                        acc[2*q] += fv.x; acc[2*q+1] += fv.y;
                    }
                }
                __half2* dst = (__half2*)(&As[s][r][c8]);
#pragma unroll
                for (int q = 0; q < 4; q++)
                    dst[q] = __floats2half2_rn(acc[2*q], acc[2*q+1]);
            } else {
                const __half* src;
                if (amode == 100)
                    src = (rg < MEML*BSZ) ? (memsh + (size_t)rg * K + k0 + c8)
                                          : (g_core_h + (size_t)(rg - MEML*BSZ) * K + k0 + c8);
                else
                    src = Ah + (size_t)rg * K + k0 + c8;
                cp16(&As[s][r][c8], src);
            }
        }
        {
            int r = t >> 2, c8 = (t & 3) * 8;
            cp16(&Bs[s][r][c8], Bh + (size_t)(n0 + r) * K + k0 + c8);
        }
        asm volatile("cp.async.commit_group;\n");
    };

    int KT = K / 32;
    stage(0, 0);
    for (int kt = 0; kt < KT; kt++) {
        int s = kt & 1;
        if (kt + 1 < KT) {
            stage((kt + 1) * 32, (kt + 1) & 1);
            asm volatile("cp.async.wait_group 1;\n");
        } else {
            asm volatile("cp.async.wait_group 0;\n");
        }
        __syncthreads();
#pragma unroll
        for (int ks = 0; ks < 32; ks += 16) {
            unsigned a[MT][4], bfrag[4][2];
#pragma unroll
            for (int mt = 0; mt < MT; mt++) {
                int r = wm + mt * 16 + g;
                a[mt][0] = *(const unsigned*)(&As[s][r][ks + 2*tg]);
                a[mt][1] = *(const unsigned*)(&As[s][r + 8][ks + 2*tg]);
                a[mt][2] = *(const unsigned*)(&As[s][r][ks + 2*tg + 8]);
                a[mt][3] = *(const unsigned*)(&As[s][r + 8][ks + 2*tg + 8]);
            }
#pragma unroll
            for (int nt = 0; nt < 4; nt++) {
                int col = wn + nt * 8 + g;
                bfrag[nt][0] = *(const unsigned*)(&Bs[s][col][ks + 2*tg]);
                bfrag[nt][1] = *(const unsigned*)(&Bs[s][col][ks + 2*tg + 8]);
            }
#pragma unroll
            for (int mt = 0; mt < MT; mt++)
#pragma unroll
                for (int nt = 0; nt < 4; nt++)
                    mma_f16(c[mt][nt][0], c[mt][nt][1], c[mt][nt][2], c[mt][nt][3],
                            a[mt][0], a[mt][1], a[mt][2], a[mt][3],
                            bfrag[nt][0], bfrag[nt][1]);
        }
        __syncthreads();
    }
#pragma unroll
    for (int mt = 0; mt < MT; mt++) {
#pragma unroll
        for (int nt = 0; nt < 4; nt++) {
            int row = m0 + wm + mt * 16 + g;
            int col = n0 + wn + nt * 8 + 2 * tg;
            float b0 = 0.f, b1 = 0.f;
            if (bias) { b0 = bias[col]; b1 = bias[col + 1]; }
            float v0 = c[mt][nt][0] + b0, v1 = c[mt][nt][1] + b1;
            float v2 = c[mt][nt][2] + b0, v3 = c[mt][nt][3] + b1;
            if (relu) {
                v0 = fmaxf(v0, 0.f); v1 = fmaxf(v1, 0.f);
                v2 = fmaxf(v2, 0.f); v3 = fmaxf(v3, 0.f);
            }
            if (Chh) {
                *(__half2*)(Chh + (size_t)row * N + col)       = __floats2half2_rn(v0, v1);
                *(__half2*)(Chh + (size_t)(row + 8) * N + col) = __floats2half2_rn(v2, v3);
            } else {
                *(float2*)(Cf + (size_t)row * N + col)       = make_float2(v0, v1);
                *(float2*)(Cf + (size_t)(row + 8) * N + col) = make_float2(v2, v3);
            }
        }
    }
}

// ---------------- shifted-BD scatter: BDpre[i][m] -> exactly one shifted slot ----------------
__device__ __forceinline__ void bd_scatter(__half* __restrict__ Cp, int i, int m, float v) {
    int mi = m + i;
    __half h = __float2half_rn(v);
    if (mi >= 1023)      Cp[(size_t)i * KL + (mi - 1023)] = h;
    else if (i > 0)      Cp[(size_t)(i - 1) * KL + (mi + 1025)] = h;
}

// ---------------- fp16 QK^T 128x128: z = bh*2 + mode; mode 0 -> AC, mode 1 -> BDs (shifted) ----------------
__global__ void __launch_bounds__(256) k_qk_f16(
        const float* __restrict__ rwb, const float* __restrict__ rrb,
        const __half* __restrict__ rk_l) {
    int z = blockIdx.z;
    int mode = z & 1, bh = z >> 1, b = bh >> 3, h = bh & 7;
    int i0 = blockIdx.y * 128, j0 = blockIdx.x * 128;
    const __half* Qp = g_heads_h + (size_t)(MEML*BSZ + b) * H3 + h*DHH;
    const __half* Kp; int kstr;
    __half* Cp;
    const float* qb;
    if (mode == 0) { Kp = g_heads_h + (size_t)b*H3 + DM + h*DHH; kstr = BSZ*H3; Cp = g_AC;  qb = rwb + h*DHH; }
    else           { Kp = rk_l + h*DHH;                          kstr = DM;     Cp = g_BDs; qb = rrb + h*DHH; }
    Cp += (size_t)bh * SEG * KL;

    __shared__ __half Qs[128][40];
    __shared__ __half Ks[128][40];
    int t = threadIdx.x;
    int lane = t & 31, g = lane >> 2, tg = lane & 3;
    int w = t >> 5;
    int wm = (w >> 1) * 32, wn = (w & 1) * 64;

#pragma unroll
    for (int i = 0; i < 2; i++) {
        int f = t + i * 256;
        int r = f >> 2, c8 = (f & 3) * 8;
        float4 raw = *(const float4*)(Qp + (size_t)(i0 + r) * (BSZ*H3) + c8);
        const __half2* hp = (const __half2*)&raw;
#pragma unroll
        for (int q = 0; q < 4; q++) {
            float2 fv = __half22float2(hp[q]);
            *(__half2*)(&Qs[r][c8 + 2*q]) =
                __floats2half2_rn(fv.x + qb[c8 + 2*q], fv.y + qb[c8 + 2*q + 1]);
        }
    }
#pragma unroll
    for (int i = 0; i < 2; i++) {
        int f = t + i * 256;
        int r = f >> 2, c8 = (f & 3) * 8;
        float4 raw = *(const float4*)(Kp + (size_t)(j0 + r) * kstr + c8);
        *(float4*)(&Ks[r][c8]) = raw;
    }
    __syncthreads();

    float c[2][8][4];
#pragma unroll
    for (int i = 0; i < 2; i++)
#pragma unroll
        for (int j = 0; j < 8; j++)
#pragma unroll
            for (int q = 0; q < 4; q++) c[i][j][q] = 0.f;

#pragma unroll
    for (int ks = 0; ks < 32; ks += 16) {
        unsigned a[2][4], bfrag[8][2];
#pragma unroll
        for (int mt = 0; mt < 2; mt++) {
            int r = wm + mt * 16 + g;
            a[mt][0] = *(const unsigned*)(&Qs[r][ks + 2*tg]);
            a[mt][1] = *(const unsigned*)(&Qs[r + 8][ks + 2*tg]);
            a[mt][2] = *(const unsigned*)(&Qs[r][ks + 2*tg + 8]);
            a[mt][3] = *(const unsigned*)(&Qs[r + 8][ks + 2*tg + 8]);
        }
#pragma unroll
        for (int nt = 0; nt < 8; nt++) {
            int col = wn + nt * 8 + g;
            bfrag[nt][0] = *(const unsigned*)(&Ks[col][ks + 2*tg]);
            bfrag[nt][1] = *(const unsigned*)(&Ks[col][ks + 2*tg + 8]);
        }
#pragma unroll
        for (int mt = 0; mt < 2; mt++)
#pragma unroll
            for (int nt = 0; nt < 8; nt++)
                mma_f16(c[mt][nt][0], c[mt][nt][1], c[mt][nt][2], c[mt][nt][3],
                        a[mt][0], a[mt][1], a[mt][2], a[mt][3],
                        bfrag[nt][0], bfrag[nt][1]);
    }
    if (mode == 0) {
#pragma unroll
        for (int mt = 0; mt < 2; mt++)
#pragma unroll
            for (int nt = 0; nt < 8; nt++) {
                int row = i0 + wm + mt * 16 + g;
                int col = j0 + wn + nt * 8 + 2 * tg;
                *(__half2*)(Cp + (size_t)row * KL + col)       = __floats2half2_rn(c[mt][nt][0], c[mt][nt][1]);
                *(__half2*)(Cp + (size_t)(row + 8) * KL + col) = __floats2half2_rn(c[mt][nt][2], c[mt][nt][3]);
            }
    } else {
#pragma unroll
        for (int mt = 0; mt < 2; mt++)
#pragma unroll
            for (int nt = 0; nt < 8; nt++) {
                int row = i0 + wm + mt * 16 + g;
                int col = j0 + wn + nt * 8 + 2 * tg;
                bd_scatter(Cp, row,     col,     c[mt][nt][0]);
                bd_scatter(Cp, row,     col + 1, c[mt][nt][1]);
                bd_scatter(Cp, row + 8, col,     c[mt][nt][2]);
                bd_scatter(Cp, row + 8, col + 1, c[mt][nt][3]);
            }
    }
}

// ---------------- fused combine + mask + softmax (pure streaming: AC + shifted BD) ----------------
__global__ void k_softmax(const unsigned char* __restrict__ mask) {
    int i = blockIdx.x, bh = blockIdx.y;
    int t = threadIdx.x;
    __half* ac = g_AC + ((size_t)bh * SEG + i) * KL;
    const __half* bds = g_BDs + ((size_t)bh * SEG + i) * KL;
    float vals[8];
    float mx = -INFINITY;
#pragma unroll
    for (int r2 = 0; r2 < 4; r2++) {
        int j0 = 2*t + r2 * 512;
        float2 a2 = __half22float2(*(const __half2*)(ac + j0));
        float2 b2 = __half22float2(*(const __half2*)(bds + j0));
        float s0 = (a2.x + b2.x) * SCALE;
        float s1 = (a2.y + b2.y) * SCALE;
        if (mask[(size_t)i * KL + j0])     s0 = -INFINITY;
        if (mask[(size_t)i * KL + j0 + 1]) s1 = -INFINITY;
        vals[r2*2]     = s0;
        vals[r2*2 + 1] = s1;
        mx = fmaxf(mx, fmaxf(s0, s1));
    }
    __shared__ float red[256];
    red[t] = mx; __syncthreads();
    for (int s2 = 128; s2 > 0; s2 >>= 1) { if (t < s2) red[t] = fmaxf(red[t], red[t+s2]); __syncthreads(); }
    float rowmax = red[0]; __syncthreads();
    float sum = 0.f;
#pragma unroll
    for (int r2 = 0; r2 < 8; r2++) { vals[r2] = __expf(vals[r2] - rowmax); sum += vals[r2]; }
    red[t] = sum; __syncthreads();
    for (int s2 = 128; s2 > 0; s2 >>= 1) { if (t < s2) red[t] += red[t+s2]; __syncthreads(); }
    float inv = 1.f / red[0];
#pragma unroll
    for (int r2 = 0; r2 < 4; r2++)
        *(__half2*)(ac + 2*t + r2*512) =
            __floats2half2_rn(vals[r2*2] * inv, vals[r2*2+1] * inv);
}

// ---------------- fp16 PV split-K: partial over j-range -> g_pvp[js] (fp16) ----------------
__global__ void k_pv_f16() {
    int bh = blockIdx.y, b = bh >> 3, h = bh & 7;
    int i0 = blockIdx.x * 64;
    int js = blockIdx.z;
    const __half* P = g_AC + (size_t)bh * SEG * KL;
    const __half* V = g_heads_h + (size_t)b * H3 + 2*DM + h*DHH;
    const int sV = BSZ*H3;
    __half* Out = g_pvp + (size_t)js * CORE_N;

    __shared__ __half Ps[64][40];
    __shared__ __half Vst[32][40];   // transposed: Vst[d][j_rel]
    int t = threadIdx.x;
    int lane = t & 31, g = lane >> 2, tg = lane & 3;
    int w = t >> 5;
    int wm = w * 16;

    float c[4][4];
#pragma unroll
    for (int j = 0; j < 4; j++)
#pragma unroll
        for (int q = 0; q < 4; q++) c[j][q] = 0.f;

    int jb = js * (KL/4), je = jb + (KL/4);
    for (int j0 = jb; j0 < je; j0 += 32) {
#pragma unroll
        for (int i = 0; i < 2; i++) {
            int f = t + i * 128;
            int r = f >> 2, c8 = (f & 3) * 8;
            float4 raw = *(const float4*)(P + (size_t)(i0 + r) * KL + j0 + c8);
            *(float4*)(&Ps[r][c8]) = raw;
        }
        {
            int jr = t >> 2, c8 = (t & 3) * 8;
            float4 raw = *(const float4*)(V + (size_t)(j0 + jr) * sV + c8);
            const __half* hv = (const __half*)&raw;
#pragma unroll
            for (int q = 0; q < 8; q++) Vst[c8 + q][jr] = hv[q];
        }
        __syncthreads();
#pragma unroll
        for (int ks = 0; ks < 32; ks += 16) {
            unsigned a0 = *(const unsigned*)(&Ps[wm + g][ks + 2*tg]);
            unsigned a1 = *(const unsigned*)(&Ps[wm + g + 8][ks + 2*tg]);
            unsigned a2 = *(const unsigned*)(&Ps[wm + g][ks + 2*tg + 8]);
            unsigned a3 = *(const unsigned*)(&Ps[wm + g + 8][ks + 2*tg + 8]);
#pragma unroll
            for (int nt = 0; nt < 4; nt++) {
                int col = nt * 8 + g;
                unsigned b0 = *(const unsigned*)(&Vst[col][ks + 2*tg]);
                unsigned b1 = *(const unsigned*)(&Vst[col][ks + 2*tg + 8]);
                mma_f16(c[nt][0], c[nt][1], c[nt][2], c[nt][3], a0, a1, a2, a3, b0, b1);
            }
        }
        __syncthreads();
    }
#pragma unroll
    for (int nt = 0; nt < 4; nt++) {
        int row = i0 + wm + g;
        int col = h*DHH + nt * 8 + 2 * tg;
        *(__half2*)(Out + (size_t)(row * BSZ + b) * DM + col)       = __floats2half2_rn(c[nt][0], c[nt][1]);
        *(__half2*)(Out + (size_t)((row + 8) * BSZ + b) * DM + col) = __floats2half2_rn(c[nt][2], c[nt][3]);
    }
}

// ---------------- residual add + LayerNorm; writes core, core_h, optional memout ----------------
__global__ void k_addln(const float* __restrict__ gamma, const float* __restrict__ beta,
                        float* __restrict__ memout) {
    int row = blockIdx.x, d = threadIdx.x;
    size_t off = (size_t)row * DM + d;
    float x = g_core[off] + g_vec[off];
    __shared__ float red[DM];
    red[d] = x; __syncthreads();
    for (int s = 128; s > 0; s >>= 1) { if (d < s) red[d] += red[d+s]; __syncthreads(); }
    float mu = red[0] * (1.f/DM); __syncthreads();
    float c = x - mu;
    red[d] = c * c; __syncthreads();
    for (int s = 128; s > 0; s >>= 1) { if (d < s) red[d] += red[d+s]; __syncthreads(); }
    float var = red[0] * (1.f/DM);
    float y = c * (1.f / sqrtf(var + 1e-5f)) * gamma[d] + beta[d];
    g_core[off] = y;
    g_core_h[off] = __float2half_rn(y);
    if (memout) memout[off] = y;
}

// ---------------- decoder ----------------
__global__ void k_dec(const float* __restrict__ Wd, const float* __restrict__ bd,
                      float* __restrict__ pred) {
    __shared__ float Wds[DM * NLD];
    int t = threadIdx.x;
    for (int i = t; i < DM * NLD; i += 256) Wds[i] = Wd[i];
    __syncthreads();
    int lane = t & 31, w = t >> 5;
    int row = blockIdx.x * 8 + w;          // row = s*BSZ + b
    int b = row & 1, s = row >> 1;
    const float* crow = g_core + (size_t)row * DM;
    float v[8];
#pragma unroll
    for (int i = 0; i < 8; i++) v[i] = crow[lane + i * 32];
#pragma unroll
    for (int l = 0; l < NLD; l++) {
        float acc = 0.f;
#pragma unroll
        for (int i = 0; i < 8; i++) acc += v[i] * Wds[(lane + i * 32) * NLD + l];
#pragma unroll
        for (int o = 16; o > 0; o >>= 1) acc += __shfl_down_sync(0xffffffffu, acc, o);
        if (lane == 0)
            pred[((size_t)b * NLD + l) * SEG + s] = acc + bd[l];
    }
}

// ---------------- host launcher ----------------
extern "C" void kernel_launch(void* const* d_in, const int* in_sizes, int n_in,
                              void* d_out, int out_size) {
    (void)in_sizes; (void)n_in; (void)out_size;
    const float* src      = (const float*)d_in[0];
    const float* mems     = (const float*)d_in[1];
    const unsigned char* mask = (const unsigned char*)d_in[2];
    const float* W_in     = (const float*)d_in[3];
    const float* b_in     = (const float*)d_in[4];
    const float* qkv_w    = (const float*)d_in[5];
    const float* r_net_w  = (const float*)d_in[6];
    const float* o_w      = (const float*)d_in[7];
    const float* ln1_g    = (const float*)d_in[8];
    const float* ln1_b    = (const float*)d_in[9];
    const float* ff_w1    = (const float*)d_in[10];
    const float* ff_b1    = (const float*)d_in[11];
    const float* ff_w2    = (const float*)d_in[12];
    const float* ff_b2    = (const float*)d_in[13];
    const float* ln2_g    = (const float*)d_in[14];
    const float* ln2_b    = (const float*)d_in[15];
    const float* W_dec    = (const float*)d_in[16];
    const float* b_dec    = (const float*)d_in[17];
    const float* r_w_bias = (const float*)d_in[18];
    const float* r_r_bias = (const float*)d_in[19];

    float* out    = (float*)d_out;
    float* pred   = out;
    float* memout = out + PRED_N;

    static __half *heads_p=nullptr, *rkh_p=nullptr, *rh_p=nullptr, *coreh_p=nullptr,
                  *midh_p=nullptr, *wqkv_p=nullptr, *wrnet_p=nullptr, *wo_p=nullptr,
                  *wff1_p=nullptr, *wff2_p=nullptr, *memsh_p=nullptr;
    static float *vec_p=nullptr;
    if (!heads_p) {
        cudaGetSymbolAddress((void**)&heads_p, g_heads_h);
        cudaGetSymbolAddress((void**)&rkh_p,   g_rk_h);
        cudaGetSymbolAddress((void**)&rh_p,    g_r_h);
        cudaGetSymbolAddress((void**)&coreh_p, g_core_h);
        cudaGetSymbolAddress((void**)&midh_p,  g_mid_h);
        cudaGetSymbolAddress((void**)&wqkv_p,  g_wqkv_h);
        cudaGetSymbolAddress((void**)&wrnet_p, g_wrnet_h);
        cudaGetSymbolAddress((void**)&wo_p,    g_wo_h);
        cudaGetSymbolAddress((void**)&wff1_p,  g_wff1_h);
        cudaGetSymbolAddress((void**)&wff2_p,  g_wff2_h);
        cudaGetSymbolAddress((void**)&memsh_p, g_mems_h);
        cudaGetSymbolAddress((void**)&vec_p,   g_vec);
    }

    // ---- prep: batched transpose+convert of all weights, convert mems, zero BD diag,
    //      input proj, pos emb ----
    k_transp_all<<<3328, dim3(32, 8)>>>(qkv_w, r_net_w, o_w, ff_w1, ff_w2);
    k_cvt<<<(LNUM*MEML*BSZ*DM/4 + 255)/256, 256>>>(mems, memsh_p, LNUM*MEML*BSZ*DM);
    k_zdiag<<<(BSZ*NH*1024 + 255)/256, 256>>>();
    k_input_proj<<<(CORE_N + 255)/256, 256>>>(src, W_in, b_in, memout);
    k_pos<<<(KL*DM + 255)/256, 256>>>();

    // rk for ALL layers, z-batched fp16 GEMM: rk_h[l] = r @ r_net_w[l]
    k_gemm_f16<64><<<dim3(DM/64, KL/64, LNUM), 256>>>(rh_p, 0, nullptr, wrnet_p,
                                                      nullptr, rkh_p, KL, DM, DM,
                                                      nullptr, 0, (size_t)DM*DM, (size_t)KL*DM);

    for (int i = 0; i < LNUM; i++) {
        // heads = [mems_h_i ; core_h] @ qkv_w[i]   [4096 x 768 x 256]
        k_gemm_f16<128><<<dim3(H3/64, (KL*BSZ)/128, 1), 256>>>(
            nullptr, 100, memsh_p + (size_t)i * MEML*BSZ*DM, wqkv_p + (size_t)i*H3*DM,
            nullptr, heads_p, KL*BSZ, H3, DM, nullptr, 0, 0, 0);
        // AC and shifted-BD in one launch (z = bh*2+mode), 128x128 tiles, fp16 mma
        k_qk_f16<<<dim3(KL/128, SEG/128, BSZ*NH*2), 256>>>(r_w_bias, r_r_bias,
                                                           rkh_p + (size_t)i*KL*DM);
        // combine + mask + softmax (fp16, pure streaming, in place over AC)
        k_softmax<<<dim3(SEG, BSZ*NH), 256>>>(mask);
        // PV split-K (fp16 partials; reduction folded into the o-proj GEMM A-load)
        k_pv_f16<<<dim3(SEG/64, BSZ*NH, 4), 128>>>();
        // attn output projection [2048 x 256 x 256], A = sum of PV partials -> g_vec fp32
        k_gemm_f16<64><<<dim3(DM/64, (SEG*BSZ)/64, 1), 256>>>(
            nullptr, 101, nullptr, wo_p + (size_t)i*DM*DM,
            vec_p, nullptr, SEG*BSZ, DM, DM, nullptr, 0, 0, 0);
        k_addln<<<SEG*BSZ, DM>>>(ln1_g + i*DM, ln1_b + i*DM, nullptr);
        // ff1 + bias + relu [2048 x 1024 x 256] -> mid_h fp16
        k_gemm_f16<128><<<dim3(DI/64, (SEG*BSZ)/128, 1), 256>>>(
            coreh_p, 0, nullptr, wff1_p + (size_t)i*DI*DM,
            nullptr, midh_p, SEG*BSZ, DI, DM, ff_b1 + i*DI, 1, 0, 0);
        // ff2 + bias [2048 x 256 x 1024] -> g_vec fp32
        k_gemm_f16<64><<<dim3(DM/64, (SEG*BSZ)/64, 1), 256>>>(
            midh_p, 0, nullptr, wff2_p + (size_t)i*DM*DI,
            vec_p, nullptr, SEG*BSZ, DM, DI, ff_b2 + i*DM, 0, 0, 0);
        k_addln<<<SEG*BSZ, DM>>>(ln2_g + i*DM, ln2_b + i*DM,
                                 memout + (size_t)(i+1)*CORE_N);
    }
    k_dec<<<(SEG*BSZ)/8, 256>>>(W_dec, b_dec, pred);
}

// round 15
// speedup vs baseline: 1.2712x; 1.2712x over previous
#include <cuda_runtime.h>
#include <cuda_fp16.h>
#include <math.h>

#define LNUM 4
#define DM   256
#define NH   8
#define DHH  32
#define DI   1024
#define SEG  1024
#define MEML 1024
#define KL   2048
#define BSZ  2
#define NLD  12
#define H3   768          // 3*H*DH
#define PRED_N (BSZ*NLD*SEG)
#define CORE_N (SEG*BSZ*DM)
#define SCALE 0.17677669529663687f   // 1/sqrt(32)

// ---------------- scratch (static device globals; no runtime allocation) ----------------
__device__ float  g_core   [CORE_N];
__device__ __half g_core_h [CORE_N];
__device__ __half g_heads_h[KL*BSZ*H3];              // qkv heads, fp16
__device__ __half g_r_h    [KL*DM];
__device__ __half g_rk_h   [LNUM*KL*DM];             // all layers, fp16
__device__ float  g_vec    [CORE_N];
__device__ __half g_mid_h  [SEG*BSZ*DI];
__device__ __half g_AC     [(size_t)BSZ*NH*SEG*KL];  // AC scores / probs (in-place, fp16)
__device__ __half g_BD     [(size_t)BSZ*NH*SEG*KL];  // pre-shift BD (fp16)
__device__ __half g_pvp    [4*CORE_N];               // PV split-K partials (fp16)
// transposed fp16 weights, [N][K] layout
__device__ __half g_wqkv_h [LNUM*H3*DM];
__device__ __half g_wrnet_h[LNUM*DM*DM];
__device__ __half g_wo_h   [LNUM*DM*DM];
__device__ __half g_wff1_h [LNUM*DI*DM];
__device__ __half g_wff2_h [LNUM*DM*DI];
__device__ __half g_mems_h [LNUM*MEML*BSZ*DM];

// ---------------- mma helpers ----------------
__device__ __forceinline__ void mma_f16(float& c0, float& c1, float& c2, float& c3,
                                        unsigned a0, unsigned a1, unsigned a2, unsigned a3,
                                        unsigned b0, unsigned b1) {
    asm volatile(
        "mma.sync.aligned.m16n8k16.row.col.f32.f16.f16.f32 "
        "{%0,%1,%2,%3},{%4,%5,%6,%7},{%8,%9},{%0,%1,%2,%3};\n"
        : "+f"(c0), "+f"(c1), "+f"(c2), "+f"(c3)
        : "r"(a0), "r"(a1), "r"(a2), "r"(a3), "r"(b0), "r"(b1));
}
__device__ __forceinline__ void cp16(void* smem_dst, const void* gsrc) {
    unsigned dst = (unsigned)__cvta_generic_to_shared(smem_dst);
    asm volatile("cp.async.ca.shared.global [%0], [%1], 16;\n" :: "r"(dst), "l"(gsrc));
}

// ---------------- batched weight prep: all 5 W[K][N] fp32 -> Wt[N][K] fp16 ----------------
// block table: qkv 768 | rnet 256 | o 256 | ff1 1024 | ff2 1024  (total 3328)
__global__ void k_transp_all(const float* __restrict__ qkv, const float* __restrict__ rnet,
                             const float* __restrict__ ow, const float* __restrict__ f1,
                             const float* __restrict__ f2) {
    __shared__ float tile[32][33];
    int bid = blockIdx.x;
    const float* W; __half* Wt; int K, N;
    if (bid < 768)       {            W = qkv;  Wt = g_wqkv_h;  K = DM; N = H3; }
    else if (bid < 1024) { bid -= 768;  W = rnet; Wt = g_wrnet_h; K = DM; N = DM; }
    else if (bid < 1280) { bid -= 1024; W = ow;   Wt = g_wo_h;    K = DM; N = DM; }
    else if (bid < 2304) { bid -= 1280; W = f1;   Wt = g_wff1_h;  K = DM; N = DI; }
    else                 { bid -= 2304; W = f2;   Wt = g_wff2_h;  K = DI; N = DM; }
    int nb = N / 32, kb = K / 32;
    int z = bid / (nb * kb);
    int rem = bid % (nb * kb);
    int ky = rem / nb, nx = rem % nb;
    W  += (size_t)z * K * N;
    Wt += (size_t)z * K * N;
    int n0 = nx * 32, k0 = ky * 32;
    int tx = threadIdx.x, ty = threadIdx.y;   // 32 x 8
    for (int r = ty; r < 32; r += 8)
        tile[r][tx] = W[(size_t)(k0 + r) * N + n0 + tx];
    __syncthreads();
    for (int r = ty; r < 32; r += 8)
        Wt[(size_t)(n0 + r) * K + k0 + tx] = __float2half_rn(tile[tx][r]);
}

// ---------------- merged misc prep: mems f32->f16 (vec4) + pos emb ----------------
// region A: idx < 512K  -> convert 4 mems elements each
// region B: next 512K   -> one pos-emb element each
#define CVT_T (LNUM*MEML*BSZ*DM/4)     // 524288
#define POS_T (KL*DM)                  // 524288
__global__ void k_prep_misc(const float* __restrict__ mems, __half* __restrict__ memsh) {
    int idx = blockIdx.x * blockDim.x + threadIdx.x;
    if (idx < CVT_T) {
        int i = idx * 4;
        float4 v = *(const float4*)(mems + i);
        __half2* o = (__half2*)(memsh + i);
        o[0] = __floats2half2_rn(v.x, v.y);
        o[1] = __floats2half2_rn(v.z, v.w);
        return;
    }
    idx -= CVT_T;
    if (idx < POS_T) {
        int d = idx & (DM - 1);
        int j = idx >> 8;
        float pos = (float)(KL - 1 - j);
        int f = (d < 128) ? d : d - 128;
        float inv = powf(10000.f, -(float)f / 128.f);
        float v = pos * inv;
        g_r_h[idx] = __float2half_rn((d < 128) ? sinf(v) : cosf(v));
    }
}

// ---------------- input projection ----------------
__global__ void k_input_proj(const float* __restrict__ src, const float* __restrict__ W_in,
                             const float* __restrict__ b_in, float* __restrict__ memout) {
    int idx = blockIdx.x * blockDim.x + threadIdx.x;
    if (idx >= CORE_N) return;
    int d  = idx & (DM - 1);
    int sb = idx >> 8;
    int b  = sb & 1;
    int s  = sb >> 1;
    float acc = b_in[d];
#pragma unroll
    for (int l = 0; l < NLD; l++)
        acc += src[((size_t)b * NLD + l) * SEG + s] * W_in[l * DM + d];
    g_core[idx] = acc;
    g_core_h[idx] = __float2half_rn(acc);
    memout[idx] = acc;   // new_mems[0] == hids[0]
}

// ---------------- fp16 GEMM, cp.async 2-stage, BK=32 ----------------
// BM in {128,64}, BN=64, 256 threads (8 warps: 4(M) x 2(N)).
// Bh is [N][K] fp16 (pre-transposed). amode: 0 normal Ah, 100 cat(memsh, g_core_h),
// 101 A = sum of 4 fp16 PV partials (converted at stage).
// Output: Cf fp32 or Chh fp16 (one non-null). blockIdx.z batches B/C by strides.
template<int BM>
__global__ void __launch_bounds__(256) k_gemm_f16(
        const __half* __restrict__ Ah, int amode, const __half* __restrict__ memsh,
        const __half* __restrict__ Bh, float* Cf, __half* Chh,
        int M, int N, int K,
        const float* __restrict__ bias, int relu,
        size_t bstride, size_t cstride) {
    constexpr int MT = BM / 64;
    Bh += (size_t)blockIdx.z * bstride;
    if (Cf)  Cf  += (size_t)blockIdx.z * cstride;
    if (Chh) Chh += (size_t)blockIdx.z * cstride;
    __shared__ __half As[2][BM][40];
    __shared__ __half Bs[2][64][40];
    int t = threadIdx.x;
    int m0 = blockIdx.y * BM, n0 = blockIdx.x * 64;
    int lane = t & 31, g = lane >> 2, tg = lane & 3;
    int w = t >> 5;
    int wm = (w >> 1) * 16 * MT, wn = (w & 1) * 32;

    float c[MT][4][4];
#pragma unroll
    for (int i = 0; i < MT; i++)
#pragma unroll
        for (int j = 0; j < 4; j++)
#pragma unroll
            for (int q = 0; q < 4; q++) c[i][j][q] = 0.f;

    auto stage = [&](int k0, int s) {
#pragma unroll
        for (int i = 0; i < MT; i++) {
            int f = t + i * 256;
            int r = f >> 2, c8 = (f & 3) * 8;
            int rg = m0 + r;
            if (amode == 101) {
                size_t off = (size_t)rg * K + k0 + c8;
                float acc[8] = {0,0,0,0,0,0,0,0};
#pragma unroll
                for (int p = 0; p < 4; p++) {
                    float4 raw = *(const float4*)(g_pvp + (size_t)p * CORE_N + off);
                    const __half2* hp = (const __half2*)&raw;
#pragma unroll
                    for (int q = 0; q < 4; q++) {
                        float2 fv = __half22float2(hp[q]);
                        acc[2*q] += fv.x; acc[2*q+1] += fv.y;
                    }
                }
                __half2* dst = (__half2*)(&As[s][r][c8]);
#pragma unroll
                for (int q = 0; q < 4; q++)
                    dst[q] = __floats2half2_rn(acc[2*q], acc[2*q+1]);
            } else {
                const __half* src;
                if (amode == 100)
                    src = (rg < MEML*BSZ) ? (memsh + (size_t)rg * K + k0 + c8)
                                          : (g_core_h + (size_t)(rg - MEML*BSZ) * K + k0 + c8);
                else
                    src = Ah + (size_t)rg * K + k0 + c8;
                cp16(&As[s][r][c8], src);
            }
        }
        {
            int r = t >> 2, c8 = (t & 3) * 8;
            cp16(&Bs[s][r][c8], Bh + (size_t)(n0 + r) * K + k0 + c8);
        }
        asm volatile("cp.async.commit_group;\n");
    };

    int KT = K / 32;
    stage(0, 0);
    for (int kt = 0; kt < KT; kt++) {
        int s = kt & 1;
        if (kt + 1 < KT) {
            stage((kt + 1) * 32, (kt + 1) & 1);
            asm volatile("cp.async.wait_group 1;\n");
        } else {
            asm volatile("cp.async.wait_group 0;\n");
        }
        __syncthreads();
#pragma unroll
        for (int ks = 0; ks < 32; ks += 16) {
            unsigned a[MT][4], bfrag[4][2];
#pragma unroll
            for (int mt = 0; mt < MT; mt++) {
                int r = wm + mt * 16 + g;
                a[mt][0] = *(const unsigned*)(&As[s][r][ks + 2*tg]);
                a[mt][1] = *(const unsigned*)(&As[s][r + 8][ks + 2*tg]);
                a[mt][2] = *(const unsigned*)(&As[s][r][ks + 2*tg + 8]);
                a[mt][3] = *(const unsigned*)(&As[s][r + 8][ks + 2*tg + 8]);
            }
#pragma unroll
            for (int nt = 0; nt < 4; nt++) {
                int col = wn + nt * 8 + g;
                bfrag[nt][0] = *(const unsigned*)(&Bs[s][col][ks + 2*tg]);
                bfrag[nt][1] = *(const unsigned*)(&Bs[s][col][ks + 2*tg + 8]);
            }
#pragma unroll
            for (int mt = 0; mt < MT; mt++)
#pragma unroll
                for (int nt = 0; nt < 4; nt++)
                    mma_f16(c[mt][nt][0], c[mt][nt][1], c[mt][nt][2], c[mt][nt][3],
                            a[mt][0], a[mt][1], a[mt][2], a[mt][3],
                            bfrag[nt][0], bfrag[nt][1]);
        }
        __syncthreads();
    }
#pragma unroll
    for (int mt = 0; mt < MT; mt++) {
#pragma unroll
        for (int nt = 0; nt < 4; nt++) {
            int row = m0 + wm + mt * 16 + g;
            int col = n0 + wn + nt * 8 + 2 * tg;
            float b0 = 0.f, b1 = 0.f;
            if (bias) { b0 = bias[col]; b1 = bias[col + 1]; }
            float v0 = c[mt][nt][0] + b0, v1 = c[mt][nt][1] + b1;
            float v2 = c[mt][nt][2] + b0, v3 = c[mt][nt][3] + b1;
            if (relu) {
                v0 = fmaxf(v0, 0.f); v1 = fmaxf(v1, 0.f);
                v2 = fmaxf(v2, 0.f); v3 = fmaxf(v3, 0.f);
            }
            if (Chh) {
                *(__half2*)(Chh + (size_t)row * N + col)       = __floats2half2_rn(v0, v1);
                *(__half2*)(Chh + (size_t)(row + 8) * N + col) = __floats2half2_rn(v2, v3);
            } else {
                *(float2*)(Cf + (size_t)row * N + col)       = make_float2(v0, v1);
                *(float2*)(Cf + (size_t)(row + 8) * N + col) = make_float2(v2, v3);
            }
        }
    }
}

// ---------------- fp16 QK^T 128x128: z = bh*2 + mode; mode 0 -> AC, mode 1 -> BDpre ----------------
__global__ void __launch_bounds__(256) k_qk_f16(
        const float* __restrict__ rwb, const float* __restrict__ rrb,
        const __half* __restrict__ rk_l) {
    int z = blockIdx.z;
    int mode = z & 1, bh = z >> 1, b = bh >> 3, h = bh & 7;
    int i0 = blockIdx.y * 128, j0 = blockIdx.x * 128;
    const __half* Qp = g_heads_h + (size_t)(MEML*BSZ + b) * H3 + h*DHH;
    const __half* Kp; int kstr;
    __half* Cp;
    const float* qb;
    if (mode == 0) { Kp = g_heads_h + (size_t)b*H3 + DM + h*DHH; kstr = BSZ*H3; Cp = g_AC; qb = rwb + h*DHH; }
    else           { Kp = rk_l + h*DHH;                          kstr = DM;     Cp = g_BD; qb = rrb + h*DHH; }
    Cp += (size_t)bh * SEG * KL;

    __shared__ __half Qs[128][40];
    __shared__ __half Ks[128][40];
    int t = threadIdx.x;
    int lane = t & 31, g = lane >> 2, tg = lane & 3;
    int w = t >> 5;
    int wm = (w >> 1) * 32, wn = (w & 1) * 64;

#pragma unroll
    for (int i = 0; i < 2; i++) {
        int f = t + i * 256;
        int r = f >> 2, c8 = (f & 3) * 8;
        float4 raw = *(const float4*)(Qp + (size_t)(i0 + r) * (BSZ*H3) + c8);
        const __half2* hp = (const __half2*)&raw;
#pragma unroll
        for (int q = 0; q < 4; q++) {
            float2 fv = __half22float2(hp[q]);
            *(__half2*)(&Qs[r][c8 + 2*q]) =
                __floats2half2_rn(fv.x + qb[c8 + 2*q], fv.y + qb[c8 + 2*q + 1]);
        }
    }
#pragma unroll
    for (int i = 0; i < 2; i++) {
        int f = t + i * 256;
        int r = f >> 2, c8 = (f & 3) * 8;
        float4 raw = *(const float4*)(Kp + (size_t)(j0 + r) * kstr + c8);
        *(float4*)(&Ks[r][c8]) = raw;
    }
    __syncthreads();

    float c[2][8][4];
#pragma unroll
    for (int i = 0; i < 2; i++)
#pragma unroll
        for (int j = 0; j < 8; j++)
#pragma unroll
            for (int q = 0; q < 4; q++) c[i][j][q] = 0.f;

#pragma unroll
    for (int ks = 0; ks < 32; ks += 16) {
        unsigned a[2][4], bfrag[8][2];
#pragma unroll
        for (int mt = 0; mt < 2; mt++) {
            int r = wm + mt * 16 + g;
            a[mt][0] = *(const unsigned*)(&Qs[r][ks + 2*tg]);
            a[mt][1] = *(const unsigned*)(&Qs[r + 8][ks + 2*tg]);
            a[mt][2] = *(const unsigned*)(&Qs[r][ks + 2*tg + 8]);
            a[mt][3] = *(const unsigned*)(&Qs[r + 8][ks + 2*tg + 8]);
        }
#pragma unroll
        for (int nt = 0; nt < 8; nt++) {
            int col = wn + nt * 8 + g;
            bfrag[nt][0] = *(const unsigned*)(&Ks[col][ks + 2*tg]);
            bfrag[nt][1] = *(const unsigned*)(&Ks[col][ks + 2*tg + 8]);
        }
#pragma unroll
        for (int mt = 0; mt < 2; mt++)
#pragma unroll
            for (int nt = 0; nt < 8; nt++)
                mma_f16(c[mt][nt][0], c[mt][nt][1], c[mt][nt][2], c[mt][nt][3],
                        a[mt][0], a[mt][1], a[mt][2], a[mt][3],
                        bfrag[nt][0], bfrag[nt][1]);
    }
#pragma unroll
    for (int mt = 0; mt < 2; mt++)
#pragma unroll
        for (int nt = 0; nt < 8; nt++) {
            int row = i0 + wm + mt * 16 + g;
            int col = j0 + wn + nt * 8 + 2 * tg;
            *(__half2*)(Cp + (size_t)row * KL + col)       = __floats2half2_rn(c[mt][nt][0], c[mt][nt][1]);
            *(__half2*)(Cp + (size_t)(row + 8) * KL + col) = __floats2half2_rn(c[mt][nt][2], c[mt][nt][3]);
        }
}

// ---------------- fused rel_shift + combine + mask + softmax (fp16 in/out, in-place) ----------------
__global__ void k_softmax(const unsigned char* __restrict__ mask) {
    int i = blockIdx.x, bh = blockIdx.y;
    int t = threadIdx.x;
    __half* ac = g_AC + ((size_t)bh * SEG + i) * KL;
    float vals[8];
    float mx = -INFINITY;
#pragma unroll
    for (int r2 = 0; r2 < 4; r2++) {
        int j0 = 2*t + r2 * 512;
        float2 a2 = __half22float2(*(const __half2*)(ac + j0));
#pragma unroll
        for (int q = 0; q < 2; q++) {
            int j = j0 + q;
            int f = SEG + i * KL + j;              // rel_shift flat index
            int a = f / (KL + 1);
            int p = f - a * (KL + 1);
            float bd = (p == 0) ? 0.f : __half2float(g_BD[((size_t)bh * SEG + a) * KL + (p - 1)]);
            float s = ((q ? a2.y : a2.x) + bd) * SCALE;
            if (mask[(size_t)i * KL + j]) s = -INFINITY;
            vals[r2*2 + q] = s;
            mx = fmaxf(mx, s);
        }
    }
    __shared__ float red[256];
    red[t] = mx; __syncthreads();
    for (int s2 = 128; s2 > 0; s2 >>= 1) { if (t < s2) red[t] = fmaxf(red[t], red[t+s2]); __syncthreads(); }
    float rowmax = red[0]; __syncthreads();
    float sum = 0.f;
#pragma unroll
    for (int r2 = 0; r2 < 8; r2++) { vals[r2] = __expf(vals[r2] - rowmax); sum += vals[r2]; }
    red[t] = sum; __syncthreads();
    for (int s2 = 128; s2 > 0; s2 >>= 1) { if (t < s2) red[t] += red[t+s2]; __syncthreads(); }
    float inv = 1.f / red[0];
#pragma unroll
    for (int r2 = 0; r2 < 4; r2++)
        *(__half2*)(ac + 2*t + r2*512) =
            __floats2half2_rn(vals[r2*2] * inv, vals[r2*2+1] * inv);
}

// ---------------- fp16 PV split-K, j-chunk 64: partial -> g_pvp[js] (fp16) ----------------
// BM=64, BN=32, 128 threads (4 warps, each 16 rows). grid (SEG/64, BSZ*NH, 4).
__global__ void k_pv_f16() {
    int bh = blockIdx.y, b = bh >> 3, h = bh & 7;
    int i0 = blockIdx.x * 64;
    int js = blockIdx.z;
    const __half* P = g_AC + (size_t)bh * SEG * KL;
    const __half* V = g_heads_h + (size_t)b * H3 + 2*DM + h*DHH;
    const int sV = BSZ*H3;
    __half* Out = g_pvp + (size_t)js * CORE_N;

    __shared__ __half Ps[64][72];
    __shared__ __half Vst[64][40];   // transposed: Vst[j_rel][d]? no -> Vst[d][j] needs [32][72]
    // NOTE: Vst holds V transposed [d][j_rel] with j_rel in 0..63 -> use [32][72]
    __shared__ __half Vst2[32][72];
    (void)Vst;
    int t = threadIdx.x;
    int lane = t & 31, g = lane >> 2, tg = lane & 3;
    int w = t >> 5;
    int wm = w * 16;

    float c[4][4];
#pragma unroll
    for (int j = 0; j < 4; j++)
#pragma unroll
        for (int q = 0; q < 4; q++) c[j][q] = 0.f;

    int jb = js * (KL/4), je = jb + (KL/4);
    for (int j0 = jb; j0 < je; j0 += 64) {
        // P tile 64x64 halves
#pragma unroll
        for (int i = 0; i < 4; i++) {
            int f = t + i * 128;
            int r = f >> 3, c8 = (f & 7) * 8;
            float4 raw = *(const float4*)(P + (size_t)(i0 + r) * KL + j0 + c8);
            *(float4*)(&Ps[r][c8]) = raw;
        }
        // V tile 64x32 halves -> transposed [32][64]
#pragma unroll
        for (int i = 0; i < 2; i++) {
            int f = t + i * 128;
            int jr = f >> 2, c8 = (f & 3) * 8;
            float4 raw = *(const float4*)(V + (size_t)(j0 + jr) * sV + c8);
            const __half* hv = (const __half*)&raw;
#pragma unroll
            for (int q = 0; q < 8; q++) Vst2[c8 + q][jr] = hv[q];
        }
        __syncthreads();
#pragma unroll
        for (int ks = 0; ks < 64; ks += 16) {
            unsigned a0 = *(const unsigned*)(&Ps[wm + g][ks + 2*tg]);
            unsigned a1 = *(const unsigned*)(&Ps[wm + g + 8][ks + 2*tg]);
            unsigned a2 = *(const unsigned*)(&Ps[wm + g][ks + 2*tg + 8]);
            unsigned a3 = *(const unsigned*)(&Ps[wm + g + 8][ks + 2*tg + 8]);
#pragma unroll
            for (int nt = 0; nt < 4; nt++) {
                int col = nt * 8 + g;
                unsigned b0 = *(const unsigned*)(&Vst2[col][ks + 2*tg]);
                unsigned b1 = *(const unsigned*)(&Vst2[col][ks + 2*tg + 8]);
                mma_f16(c[nt][0], c[nt][1], c[nt][2], c[nt][3], a0, a1, a2, a3, b0, b1);
            }
        }
        __syncthreads();
    }
#pragma unroll
    for (int nt = 0; nt < 4; nt++) {
        int row = i0 + wm + g;
        int col = h*DHH + nt * 8 + 2 * tg;
        *(__half2*)(Out + (size_t)(row * BSZ + b) * DM + col)       = __floats2half2_rn(c[nt][0], c[nt][1]);
        *(__half2*)(Out + (size_t)((row + 8) * BSZ + b) * DM + col) = __floats2half2_rn(c[nt][2], c[nt][3]);
    }
}

// ---------------- residual add + LayerNorm; writes core, core_h, optional memout ----------------
__global__ void k_addln(const float* __restrict__ gamma, const float* __restrict__ beta,
                        float* __restrict__ memout) {
    int row = blockIdx.x, d = threadIdx.x;
    size_t off = (size_t)row * DM + d;
    float x = g_core[off] + g_vec[off];
    __shared__ float red[DM];
    red[d] = x; __syncthreads();
    for (int s = 128; s > 0; s >>= 1) { if (d < s) red[d] += red[d+s]; __syncthreads(); }
    float mu = red[0] * (1.f/DM); __syncthreads();
    float c = x - mu;
    red[d] = c * c; __syncthreads();
    for (int s = 128; s > 0; s >>= 1) { if (d < s) red[d] += red[d+s]; __syncthreads(); }
    float var = red[0] * (1.f/DM);
    float y = c * (1.f / sqrtf(var + 1e-5f)) * gamma[d] + beta[d];
    g_core[off] = y;
    g_core_h[off] = __float2half_rn(y);
    if (memout) memout[off] = y;
}

// ---------------- decoder ----------------
__global__ void k_dec(const float* __restrict__ Wd, const float* __restrict__ bd,
                      float* __restrict__ pred) {
    __shared__ float Wds[DM * NLD];
    int t = threadIdx.x;
    for (int i = t; i < DM * NLD; i += 256) Wds[i] = Wd[i];
    __syncthreads();
    int lane = t & 31, w = t >> 5;
    int row = blockIdx.x * 8 + w;          // row = s*BSZ + b
    int b = row & 1, s = row >> 1;
    const float* crow = g_core + (size_t)row * DM;
    float v[8];
#pragma unroll
    for (int i = 0; i < 8; i++) v[i] = crow[lane + i * 32];
#pragma unroll
    for (int l = 0; l < NLD; l++) {
        float acc = 0.f;
#pragma unroll
        for (int i = 0; i < 8; i++) acc += v[i] * Wds[(lane + i * 32) * NLD + l];
#pragma unroll
        for (int o = 16; o > 0; o >>= 1) acc += __shfl_down_sync(0xffffffffu, acc, o);
        if (lane == 0)
            pred[((size_t)b * NLD + l) * SEG + s] = acc + bd[l];
    }
}

// ---------------- host launcher ----------------
extern "C" void kernel_launch(void* const* d_in, const int* in_sizes, int n_in,
                              void* d_out, int out_size) {
    (void)in_sizes; (void)n_in; (void)out_size;
    const float* src      = (const float*)d_in[0];
    const float* mems     = (const float*)d_in[1];
    const unsigned char* mask = (const unsigned char*)d_in[2];
    const float* W_in     = (const float*)d_in[3];
    const float* b_in     = (const float*)d_in[4];
    const float* qkv_w    = (const float*)d_in[5];
    const float* r_net_w  = (const float*)d_in[6];
    const float* o_w      = (const float*)d_in[7];
    const float* ln1_g    = (const float*)d_in[8];
    const float* ln1_b    = (const float*)d_in[9];
    const float* ff_w1    = (const float*)d_in[10];
    const float* ff_b1    = (const float*)d_in[11];
    const float* ff_w2    = (const float*)d_in[12];
    const float* ff_b2    = (const float*)d_in[13];
    const float* ln2_g    = (const float*)d_in[14];
    const float* ln2_b    = (const float*)d_in[15];
    const float* W_dec    = (const float*)d_in[16];
    const float* b_dec    = (const float*)d_in[17];
    const float* r_w_bias = (const float*)d_in[18];
    const float* r_r_bias = (const float*)d_in[19];

    float* out    = (float*)d_out;
    float* pred   = out;
    float* memout = out + PRED_N;

    static __half *heads_p=nullptr, *rkh_p=nullptr, *rh_p=nullptr, *coreh_p=nullptr,
                  *midh_p=nullptr, *wqkv_p=nullptr, *wrnet_p=nullptr, *wo_p=nullptr,
                  *wff1_p=nullptr, *wff2_p=nullptr, *memsh_p=nullptr;
    static float *vec_p=nullptr;
    if (!heads_p) {
        cudaGetSymbolAddress((void**)&heads_p, g_heads_h);
        cudaGetSymbolAddress((void**)&rkh_p,   g_rk_h);
        cudaGetSymbolAddress((void**)&rh_p,    g_r_h);
        cudaGetSymbolAddress((void**)&coreh_p, g_core_h);
        cudaGetSymbolAddress((void**)&midh_p,  g_mid_h);
        cudaGetSymbolAddress((void**)&wqkv_p,  g_wqkv_h);
        cudaGetSymbolAddress((void**)&wrnet_p, g_wrnet_h);
        cudaGetSymbolAddress((void**)&wo_p,    g_wo_h);
        cudaGetSymbolAddress((void**)&wff1_p,  g_wff1_h);
        cudaGetSymbolAddress((void**)&wff2_p,  g_wff2_h);
        cudaGetSymbolAddress((void**)&memsh_p, g_mems_h);
        cudaGetSymbolAddress((void**)&vec_p,   g_vec);
    }

    // ---- prep: batched weight transpose, merged misc (mems cvt + pos), input proj ----
    k_transp_all<<<3328, dim3(32, 8)>>>(qkv_w, r_net_w, o_w, ff_w1, ff_w2);
    k_prep_misc<<<(CVT_T + POS_T + 255)/256, 256>>>(mems, memsh_p);
    k_input_proj<<<(CORE_N + 255)/256, 256>>>(src, W_in, b_in, memout);

    // rk for ALL layers, z-batched fp16 GEMM: rk_h[l] = r @ r_net_w[l]
    k_gemm_f16<64><<<dim3(DM/64, KL/64, LNUM), 256>>>(rh_p, 0, nullptr, wrnet_p,
                                                      nullptr, rkh_p, KL, DM, DM,
                                                      nullptr, 0, (size_t)DM*DM, (size_t)KL*DM);

    for (int i = 0; i < LNUM; i++) {
        // heads = [mems_h_i ; core_h] @ qkv_w[i]   [4096 x 768 x 256]
        k_gemm_f16<128><<<dim3(H3/64, (KL*BSZ)/128, 1), 256>>>(
            nullptr, 100, memsh_p + (size_t)i * MEML*BSZ*DM, wqkv_p + (size_t)i*H3*DM,
            nullptr, heads_p, KL*BSZ, H3, DM, nullptr, 0, 0, 0);
        // AC and BDpre in one launch (z = bh*2+mode), 128x128 tiles, fp16 mma
        k_qk_f16<<<dim3(KL/128, SEG/128, BSZ*NH*2), 256>>>(r_w_bias, r_r_bias,
                                                           rkh_p + (size_t)i*KL*DM);
        // shift + combine + mask + softmax (fp16 in place)
        k_softmax<<<dim3(SEG, BSZ*NH), 256>>>(mask);
        // PV split-K (fp16 partials; reduction folded into the o-proj GEMM A-load)
        k_pv_f16<<<dim3(SEG/64, BSZ*NH, 4), 128>>>();
        // attn output projection [2048 x 256 x 256], A = sum of PV partials -> g_vec fp32
        k_gemm_f16<64><<<dim3(DM/64, (SEG*BSZ)/64, 1), 256>>>(
            nullptr, 101, nullptr, wo_p + (size_t)i*DM*DM,
            vec_p, nullptr, SEG*BSZ, DM, DM, nullptr, 0, 0, 0);
        k_addln<<<SEG*BSZ, DM>>>(ln1_g + i*DM, ln1_b + i*DM, nullptr);
        // ff1 + bias + relu [2048 x 1024 x 256] -> mid_h fp16
        k_gemm_f16<128><<<dim3(DI/64, (SEG*BSZ)/128, 1), 256>>>(
            coreh_p, 0, nullptr, wff1_p + (size_t)i*DI*DM,
            nullptr, midh_p, SEG*BSZ, DI, DM, ff_b1 + i*DI, 1, 0, 0);
        // ff2 + bias [2048 x 256 x 1024] -> g_vec fp32
        k_gemm_f16<64><<<dim3(DM/64, (SEG*BSZ)/64, 1), 256>>>(
            midh_p, 0, nullptr, wff2_p + (size_t)i*DM*DI,
            vec_p, nullptr, SEG*BSZ, DM, DI, ff_b2 + i*DM, 0, 0, 0);
        k_addln<<<SEG*BSZ, DM>>>(ln2_g + i*DM, ln2_b + i*DM,
                                 memout + (size_t)(i+1)*CORE_N);
    }
    k_dec<<<(SEG*BSZ)/8, 256>>>(W_dec, b_dec, pred);
}

// round 17
// speedup vs baseline: 1.2830x; 1.0093x over previous
#include <cuda_runtime.h>
#include <cuda_fp16.h>
#include <math.h>

#define LNUM 4
#define DM   256
#define NH   8
#define DHH  32
#define DI   1024
#define SEG  1024
#define MEML 1024
#define KL   2048
#define BSZ  2
#define NLD  12
#define H3   768          // 3*H*DH
#define PRED_N (BSZ*NLD*SEG)
#define CORE_N (SEG*BSZ*DM)
#define SCALE 0.17677669529663687f   // 1/sqrt(32)

// ---------------- scratch (static device globals; no runtime allocation) ----------------
__device__ float  g_core   [CORE_N];
__device__ __half g_core_h [CORE_N];
__device__ __half g_heads_h[KL*BSZ*H3];              // qkv heads, fp16
__device__ __half g_r_h    [KL*DM];
__device__ __half g_rk_h   [LNUM*KL*DM];             // all layers, fp16
__device__ float  g_vec    [CORE_N];
__device__ __half g_mid_h  [SEG*BSZ*DI];
__device__ __half g_AC     [(size_t)BSZ*NH*SEG*KL];  // AC scores / probs (in-place, fp16)
__device__ __half g_BD     [(size_t)BSZ*NH*SEG*KL];  // pre-shift BD (fp16)
__device__ __half g_pvp    [4*CORE_N];               // PV split-K partials (fp16)
// transposed fp16 weights, [N][K] layout
__device__ __half g_wqkv_h [LNUM*H3*DM];
__device__ __half g_wrnet_h[LNUM*DM*DM];
__device__ __half g_wo_h   [LNUM*DM*DM];
__device__ __half g_wff1_h [LNUM*DI*DM];
__device__ __half g_wff2_h [LNUM*DM*DI];
__device__ __half g_mems_h [LNUM*MEML*BSZ*DM];

// ---------------- mma / ldmatrix helpers ----------------
__device__ __forceinline__ void mma_f16(float& c0, float& c1, float& c2, float& c3,
                                        unsigned a0, unsigned a1, unsigned a2, unsigned a3,
                                        unsigned b0, unsigned b1) {
    asm volatile(
        "mma.sync.aligned.m16n8k16.row.col.f32.f16.f16.f32 "
        "{%0,%1,%2,%3},{%4,%5,%6,%7},{%8,%9},{%0,%1,%2,%3};\n"
        : "+f"(c0), "+f"(c1), "+f"(c2), "+f"(c3)
        : "r"(a0), "r"(a1), "r"(a2), "r"(a3), "r"(b0), "r"(b1));
}
__device__ __forceinline__ void cp16(void* smem_dst, const void* gsrc) {
    unsigned dst = (unsigned)__cvta_generic_to_shared(smem_dst);
    asm volatile("cp.async.ca.shared.global [%0], [%1], 16;\n" :: "r"(dst), "l"(gsrc));
}
__device__ __forceinline__ void ldm_x4(unsigned& r0, unsigned& r1, unsigned& r2, unsigned& r3,
                                       const __half* p) {
    unsigned addr = (unsigned)__cvta_generic_to_shared(p);
    asm volatile("ldmatrix.sync.aligned.m8n8.x4.shared.b16 {%0,%1,%2,%3}, [%4];\n"
                 : "=r"(r0), "=r"(r1), "=r"(r2), "=r"(r3) : "r"(addr));
}

// ---------------- batched weight prep: all 5 W[K][N] fp32 -> Wt[N][K] fp16 ----------------
__global__ void k_transp_all(const float* __restrict__ qkv, const float* __restrict__ rnet,
                             const float* __restrict__ ow, const float* __restrict__ f1,
                             const float* __restrict__ f2) {
    __shared__ float tile[32][33];
    int bid = blockIdx.x;
    const float* W; __half* Wt; int K, N;
    if (bid < 768)       {            W = qkv;  Wt = g_wqkv_h;  K = DM; N = H3; }
    else if (bid < 1024) { bid -= 768;  W = rnet; Wt = g_wrnet_h; K = DM; N = DM; }
    else if (bid < 1280) { bid -= 1024; W = ow;   Wt = g_wo_h;    K = DM; N = DM; }
    else if (bid < 2304) { bid -= 1280; W = f1;   Wt = g_wff1_h;  K = DM; N = DI; }
    else                 { bid -= 2304; W = f2;   Wt = g_wff2_h;  K = DI; N = DM; }
    int nb = N / 32, kb = K / 32;
    int z = bid / (nb * kb);
    int rem = bid % (nb * kb);
    int ky = rem / nb, nx = rem % nb;
    W  += (size_t)z * K * N;
    Wt += (size_t)z * K * N;
    int n0 = nx * 32, k0 = ky * 32;
    int tx = threadIdx.x, ty = threadIdx.y;   // 32 x 8
    for (int r = ty; r < 32; r += 8)
        tile[r][tx] = W[(size_t)(k0 + r) * N + n0 + tx];
    __syncthreads();
    for (int r = ty; r < 32; r += 8)
        Wt[(size_t)(n0 + r) * K + k0 + tx] = __float2half_rn(tile[tx][r]);
}

// ---------------- merged misc prep: mems f32->f16 (vec4) + pos emb ----------------
#define CVT_T (LNUM*MEML*BSZ*DM/4)     // 524288
#define POS_T (KL*DM)                  // 524288
__global__ void k_prep_misc(const float* __restrict__ mems, __half* __restrict__ memsh) {
    int idx = blockIdx.x * blockDim.x + threadIdx.x;
    if (idx < CVT_T) {
        int i = idx * 4;
        float4 v = *(const float4*)(mems + i);
        __half2* o = (__half2*)(memsh + i);
        o[0] = __floats2half2_rn(v.x, v.y);
        o[1] = __floats2half2_rn(v.z, v.w);
        return;
    }
    idx -= CVT_T;
    if (idx < POS_T) {
        int d = idx & (DM - 1);
        int j = idx >> 8;
        float pos = (float)(KL - 1 - j);
        int f = (d < 128) ? d : d - 128;
        float inv = powf(10000.f, -(float)f / 128.f);
        float v = pos * inv;
        g_r_h[idx] = __float2half_rn((d < 128) ? sinf(v) : cosf(v));
    }
}

// ---------------- input projection ----------------
__global__ void k_input_proj(const float* __restrict__ src, const float* __restrict__ W_in,
                             const float* __restrict__ b_in, float* __restrict__ memout) {
    int idx = blockIdx.x * blockDim.x + threadIdx.x;
    if (idx >= CORE_N) return;
    int d  = idx & (DM - 1);
    int sb = idx >> 8;
    int b  = sb & 1;
    int s  = sb >> 1;
    float acc = b_in[d];
#pragma unroll
    for (int l = 0; l < NLD; l++)
        acc += src[((size_t)b * NLD + l) * SEG + s] * W_in[l * DM + d];
    g_core[idx] = acc;
    g_core_h[idx] = __float2half_rn(acc);
    memout[idx] = acc;   // new_mems[0] == hids[0]
}

// ---------------- fp16 GEMM, cp.async 2-stage, BK=32, ldmatrix fragments ----------------
template<int BM>
__global__ void __launch_bounds__(256) k_gemm_f16(
        const __half* __restrict__ Ah, int amode, const __half* __restrict__ memsh,
        const __half* __restrict__ Bh, float* Cf, __half* Chh,
        int M, int N, int K,
        const float* __restrict__ bias, int relu,
        size_t bstride, size_t cstride) {
    constexpr int MT = BM / 64;
    Bh += (size_t)blockIdx.z * bstride;
    if (Cf)  Cf  += (size_t)blockIdx.z * cstride;
    if (Chh) Chh += (size_t)blockIdx.z * cstride;
    __shared__ __half As[2][BM][40];
    __shared__ __half Bs[2][64][40];
    int t = threadIdx.x;
    int m0 = blockIdx.y * BM, n0 = blockIdx.x * 64;
    int lane = t & 31, g = lane >> 2, tg = lane & 3;
    int w = t >> 5;
    int wm = (w >> 1) * 16 * MT, wn = (w & 1) * 32;
    // ldmatrix per-lane offsets
    int a_r = (lane & 7) + ((lane >> 3) & 1) * 8;
    int a_c = (lane >> 4) * 8;
    int b_r = (lane & 7) + (lane >> 4) * 8;
    int b_c = ((lane >> 3) & 1) * 8;

    float c[MT][4][4];
#pragma unroll
    for (int i = 0; i < MT; i++)
#pragma unroll
        for (int j = 0; j < 4; j++)
#pragma unroll
            for (int q = 0; q < 4; q++) c[i][j][q] = 0.f;

    auto stage = [&](int k0, int s) {
#pragma unroll
        for (int i = 0; i < MT; i++) {
            int f = t + i * 256;
            int r = f >> 2, c8 = (f & 3) * 8;
            int rg = m0 + r;
            if (amode == 101) {
                size_t off = (size_t)rg * K + k0 + c8;
                float acc[8] = {0,0,0,0,0,0,0,0};
#pragma unroll
                for (int p = 0; p < 4; p++) {
                    float4 raw = *(const float4*)(g_pvp + (size_t)p * CORE_N + off);
                    const __half2* hp = (const __half2*)&raw;
#pragma unroll
                    for (int q = 0; q < 4; q++) {
                        float2 fv = __half22float2(hp[q]);
                        acc[2*q] += fv.x; acc[2*q+1] += fv.y;
                    }
                }
                __half2* dst = (__half2*)(&As[s][r][c8]);
#pragma unroll
                for (int q = 0; q < 4; q++)
                    dst[q] = __floats2half2_rn(acc[2*q], acc[2*q+1]);
            } else {
                const __half* src;
                if (amode == 100)
                    src = (rg < MEML*BSZ) ? (memsh + (size_t)rg * K + k0 + c8)
                                          : (g_core_h + (size_t)(rg - MEML*BSZ) * K + k0 + c8);
                else
                    src = Ah + (size_t)rg * K + k0 + c8;
                cp16(&As[s][r][c8], src);
            }
        }
        {
            int r = t >> 2, c8 = (t & 3) * 8;
            cp16(&Bs[s][r][c8], Bh + (size_t)(n0 + r) * K + k0 + c8);
        }
        asm volatile("cp.async.commit_group;\n");
    };

    int KT = K / 32;
    stage(0, 0);
    for (int kt = 0; kt < KT; kt++) {
        int s = kt & 1;
        if (kt + 1 < KT) {
            stage((kt + 1) * 32, (kt + 1) & 1);
            asm volatile("cp.async.wait_group 1;\n");
        } else {
            asm volatile("cp.async.wait_group 0;\n");
        }
        __syncthreads();
#pragma unroll
        for (int ks = 0; ks < 32; ks += 16) {
            unsigned a[MT][4], bfrag[4][2];
#pragma unroll
            for (int mt = 0; mt < MT; mt++)
                ldm_x4(a[mt][0], a[mt][1], a[mt][2], a[mt][3],
                       &As[s][wm + mt*16 + a_r][ks + a_c]);
#pragma unroll
            for (int np = 0; np < 2; np++)
                ldm_x4(bfrag[2*np][0], bfrag[2*np][1], bfrag[2*np+1][0], bfrag[2*np+1][1],
                       &Bs[s][wn + np*16 + b_r][ks + b_c]);
#pragma unroll
            for (int mt = 0; mt < MT; mt++)
#pragma unroll
                for (int nt = 0; nt < 4; nt++)
                    mma_f16(c[mt][nt][0], c[mt][nt][1], c[mt][nt][2], c[mt][nt][3],
                            a[mt][0], a[mt][1], a[mt][2], a[mt][3],
                            bfrag[nt][0], bfrag[nt][1]);
        }
        __syncthreads();
    }
#pragma unroll
    for (int mt = 0; mt < MT; mt++) {
#pragma unroll
        for (int nt = 0; nt < 4; nt++) {
            int row = m0 + wm + mt * 16 + g;
            int col = n0 + wn + nt * 8 + 2 * tg;
            float b0 = 0.f, b1 = 0.f;
            if (bias) { b0 = bias[col]; b1 = bias[col + 1]; }
            float v0 = c[mt][nt][0] + b0, v1 = c[mt][nt][1] + b1;
            float v2 = c[mt][nt][2] + b0, v3 = c[mt][nt][3] + b1;
            if (relu) {
                v0 = fmaxf(v0, 0.f); v1 = fmaxf(v1, 0.f);
                v2 = fmaxf(v2, 0.f); v3 = fmaxf(v3, 0.f);
            }
            if (Chh) {
                *(__half2*)(Chh + (size_t)row * N + col)       = __floats2half2_rn(v0, v1);
                *(__half2*)(Chh + (size_t)(row + 8) * N + col) = __floats2half2_rn(v2, v3);
            } else {
                *(float2*)(Cf + (size_t)row * N + col)       = make_float2(v0, v1);
                *(float2*)(Cf + (size_t)(row + 8) * N + col) = make_float2(v2, v3);
            }
        }
    }
}

// ---------------- fp16 QK^T 128x128, ldmatrix: z = bh*2 + mode ----------------
__global__ void __launch_bounds__(256) k_qk_f16(
        const float* __restrict__ rwb, const float* __restrict__ rrb,
        const __half* __restrict__ rk_l) {
    int z = blockIdx.z;
    int mode = z & 1, bh = z >> 1, b = bh >> 3, h = bh & 7;
    int i0 = blockIdx.y * 128, j0 = blockIdx.x * 128;
    const __half* Qp = g_heads_h + (size_t)(MEML*BSZ + b) * H3 + h*DHH;
    const __half* Kp; int kstr;
    __half* Cp;
    const float* qb;
    if (mode == 0) { Kp = g_heads_h + (size_t)b*H3 + DM + h*DHH; kstr = BSZ*H3; Cp = g_AC; qb = rwb + h*DHH; }
    else           { Kp = rk_l + h*DHH;                          kstr = DM;     Cp = g_BD; qb = rrb + h*DHH; }
    Cp += (size_t)bh * SEG * KL;

    __shared__ __half Qs[128][40];
    __shared__ __half Ks[128][40];
    int t = threadIdx.x;
    int lane = t & 31, g = lane >> 2, tg = lane & 3;
    int w = t >> 5;
    int wm = (w >> 1) * 32, wn = (w & 1) * 64;
    int a_r = (lane & 7) + ((lane >> 3) & 1) * 8;
    int a_c = (lane >> 4) * 8;
    int b_r = (lane & 7) + (lane >> 4) * 8;
    int b_c = ((lane >> 3) & 1) * 8;

#pragma unroll
    for (int i = 0; i < 2; i++) {
        int f = t + i * 256;
        int r = f >> 2, c8 = (f & 3) * 8;
        float4 raw = *(const float4*)(Qp + (size_t)(i0 + r) * (BSZ*H3) + c8);
        const __half2* hp = (const __half2*)&raw;
#pragma unroll
        for (int q = 0; q < 4; q++) {
            float2 fv = __half22float2(hp[q]);
            *(__half2*)(&Qs[r][c8 + 2*q]) =
                __floats2half2_rn(fv.x + qb[c8 + 2*q], fv.y + qb[c8 + 2*q + 1]);
        }
    }
#pragma unroll
    for (int i = 0; i < 2; i++) {
        int f = t + i * 256;
        int r = f >> 2, c8 = (f & 3) * 8;
        float4 raw = *(const float4*)(Kp + (size_t)(j0 + r) * kstr + c8);
        *(float4*)(&Ks[r][c8]) = raw;
    }
    __syncthreads();

    float c[2][8][4];
#pragma unroll
    for (int i = 0; i < 2; i++)
#pragma unroll
        for (int j = 0; j < 8; j++)
#pragma unroll
            for (int q = 0; q < 4; q++) c[i][j][q] = 0.f;

#pragma unroll
    for (int ks = 0; ks < 32; ks += 16) {
        unsigned a[2][4], bfrag[8][2];
#pragma unroll
        for (int mt = 0; mt < 2; mt++)
            ldm_x4(a[mt][0], a[mt][1], a[mt][2], a[mt][3],
                   &Qs[wm + mt*16 + a_r][ks + a_c]);
#pragma unroll
        for (int np = 0; np < 4; np++)
            ldm_x4(bfrag[2*np][0], bfrag[2*np][1], bfrag[2*np+1][0], bfrag[2*np+1][1],
                   &Ks[wn + np*16 + b_r][ks + b_c]);
#pragma unroll
        for (int mt = 0; mt < 2; mt++)
#pragma unroll
            for (int nt = 0; nt < 8; nt++)
                mma_f16(c[mt][nt][0], c[mt][nt][1], c[mt][nt][2], c[mt][nt][3],
                        a[mt][0], a[mt][1], a[mt][2], a[mt][3],
                        bfrag[nt][0], bfrag[nt][1]);
    }
#pragma unroll
    for (int mt = 0; mt < 2; mt++)
#pragma unroll
        for (int nt = 0; nt < 8; nt++) {
            int row = i0 + wm + mt * 16 + g;
            int col = j0 + wn + nt * 8 + 2 * tg;
            *(__half2*)(Cp + (size_t)row * KL + col)       = __floats2half2_rn(c[mt][nt][0], c[mt][nt][1]);
            *(__half2*)(Cp + (size_t)(row + 8) * KL + col) = __floats2half2_rn(c[mt][nt][2], c[mt][nt][3]);
        }
}

// ---------------- fused rel_shift + combine + mask + softmax (fp16 in/out, in-place) ----------------
__global__ void k_softmax(const unsigned char* __restrict__ mask) {
    int i = blockIdx.x, bh = blockIdx.y;
    int t = threadIdx.x;
    __half* ac = g_AC + ((size_t)bh * SEG + i) * KL;
    float vals[8];
    float mx = -INFINITY;
#pragma unroll
    for (int r2 = 0; r2 < 4; r2++) {
        int j0 = 2*t + r2 * 512;
        float2 a2 = __half22float2(*(const __half2*)(ac + j0));
#pragma unroll
        for (int q = 0; q < 2; q++) {
            int j = j0 + q;
            int f = SEG + i * KL + j;              // rel_shift flat index
            int a = f / (KL + 1);
            int p = f - a * (KL + 1);
            float bd = (p == 0) ? 0.f : __half2float(g_BD[((size_t)bh * SEG + a) * KL + (p - 1)]);
            float s = ((q ? a2.y : a2.x) + bd) * SCALE;
            if (mask[(size_t)i * KL + j]) s = -INFINITY;
            vals[r2*2 + q] = s;
            mx = fmaxf(mx, s);
        }
    }
    __shared__ float red[256];
    red[t] = mx; __syncthreads();
    for (int s2 = 128; s2 > 0; s2 >>= 1) { if (t < s2) red[t] = fmaxf(red[t], red[t+s2]); __syncthreads(); }
    float rowmax = red[0]; __syncthreads();
    float sum = 0.f;
#pragma unroll
    for (int r2 = 0; r2 < 8; r2++) { vals[r2] = __expf(vals[r2] - rowmax); sum += vals[r2]; }
    red[t] = sum; __syncthreads();
    for (int s2 = 128; s2 > 0; s2 >>= 1) { if (t < s2) red[t] += red[t+s2]; __syncthreads(); }
    float inv = 1.f / red[0];
#pragma unroll
    for (int r2 = 0; r2 < 4; r2++)
        *(__half2*)(ac + 2*t + r2*512) =
            __floats2half2_rn(vals[r2*2] * inv, vals[r2*2+1] * inv);
}

// ---------------- fp16 PV split-K, j-chunk 64, ldmatrix: partial -> g_pvp[js] (fp16) ----------------
__global__ void k_pv_f16() {
    int bh = blockIdx.y, b = bh >> 3, h = bh & 7;
    int i0 = blockIdx.x * 64;
    int js = blockIdx.z;
    const __half* P = g_AC + (size_t)bh * SEG * KL;
    const __half* V = g_heads_h + (size_t)b * H3 + 2*DM + h*DHH;
    const int sV = BSZ*H3;
    __half* Out = g_pvp + (size_t)js * CORE_N;

    __shared__ __half Ps[64][72];
    __shared__ __half Vst[32][72];   // transposed: Vst[d][j_rel], j_rel 0..63
    int t = threadIdx.x;
    int lane = t & 31, g = lane >> 2, tg = lane & 3;
    int w = t >> 5;
    int wm = w * 16;
    int a_r = (lane & 7) + ((lane >> 3) & 1) * 8;
    int a_c = (lane >> 4) * 8;
    int b_r = (lane & 7) + (lane >> 4) * 8;
    int b_c = ((lane >> 3) & 1) * 8;

    float c[4][4];
#pragma unroll
    for (int j = 0; j < 4; j++)
#pragma unroll
        for (int q = 0; q < 4; q++) c[j][q] = 0.f;

    int jb = js * (KL/4), je = jb + (KL/4);
    for (int j0 = jb; j0 < je; j0 += 64) {
        // P tile 64x64 halves
#pragma unroll
        for (int i = 0; i < 4; i++) {
            int f = t + i * 128;
            int r = f >> 3, c8 = (f & 7) * 8;
            float4 raw = *(const float4*)(P + (size_t)(i0 + r) * KL + j0 + c8);
            *(float4*)(&Ps[r][c8]) = raw;
        }
        // V tile 64x32 halves -> transposed [32][64]
#pragma unroll
        for (int i = 0; i < 2; i++) {
            int f = t + i * 128;
            int jr = f >> 2, c8 = (f & 3) * 8;
            float4 raw = *(const float4*)(V + (size_t)(j0 + jr) * sV + c8);
            const __half* hv = (const __half*)&raw;
#pragma unroll
            for (int q = 0; q < 8; q++) Vst[c8 + q][jr] = hv[q];
        }
        __syncthreads();
#pragma unroll
        for (int ks = 0; ks < 64; ks += 16) {
            unsigned a0, a1, a2, a3, bfrag[4][2];
            ldm_x4(a0, a1, a2, a3, &Ps[wm + a_r][ks + a_c]);
#pragma unroll
            for (int np = 0; np < 2; np++)
                ldm_x4(bfrag[2*np][0], bfrag[2*np][1], bfrag[2*np+1][0], bfrag[2*np+1][1],
                       &Vst[np*16 + b_r][ks + b_c]);
#pragma unroll
            for (int nt = 0; nt < 4; nt++)
                mma_f16(c[nt][0], c[nt][1], c[nt][2], c[nt][3], a0, a1, a2, a3,
                        bfrag[nt][0], bfrag[nt][1]);
        }
        __syncthreads();
    }
#pragma unroll
    for (int nt = 0; nt < 4; nt++) {
        int row = i0 + wm + g;
        int col = h*DHH + nt * 8 + 2 * tg;
        *(__half2*)(Out + (size_t)(row * BSZ + b) * DM + col)       = __floats2half2_rn(c[nt][0], c[nt][1]);
        *(__half2*)(Out + (size_t)((row + 8) * BSZ + b) * DM + col) = __floats2half2_rn(c[nt][2], c[nt][3]);
    }
}

// ---------------- residual add + LayerNorm; writes core, core_h, optional memout ----------------
__global__ void k_addln(const float* __restrict__ gamma, const float* __restrict__ beta,
                        float* __restrict__ memout) {
    int row = blockIdx.x, d = threadIdx.x;
    size_t off = (size_t)row * DM + d;
    float x = g_core[off] + g_vec[off];
    __shared__ float red[DM];
    red[d] = x; __syncthreads();
    for (int s = 128; s > 0; s >>= 1) { if (d < s) red[d] += red[d+s]; __syncthreads(); }
    float mu = red[0] * (1.f/DM); __syncthreads();
    float c = x - mu;
    red[d] = c * c; __syncthreads();
    for (int s = 128; s > 0; s >>= 1) { if (d < s) red[d] += red[d+s]; __syncthreads(); }
    float var = red[0] * (1.f/DM);
    float y = c * (1.f / sqrtf(var + 1e-5f)) * gamma[d] + beta[d];
    g_core[off] = y;
    g_core_h[off] = __float2half_rn(y);
    if (memout) memout[off] = y;
}

// ---------------- decoder ----------------
__global__ void k_dec(const float* __restrict__ Wd, const float* __restrict__ bd,
                      float* __restrict__ pred) {
    __shared__ float Wds[DM * NLD];
    int t = threadIdx.x;
    for (int i = t; i < DM * NLD; i += 256) Wds[i] = Wd[i];
    __syncthreads();
    int lane = t & 31, w = t >> 5;
    int row = blockIdx.x * 8 + w;          // row = s*BSZ + b
    int b = row & 1, s = row >> 1;
    const float* crow = g_core + (size_t)row * DM;
    float v[8];
#pragma unroll
    for (int i = 0; i < 8; i++) v[i] = crow[lane + i * 32];
#pragma unroll
    for (int l = 0; l < NLD; l++) {
        float acc = 0.f;
#pragma unroll
        for (int i = 0; i < 8; i++) acc += v[i] * Wds[(lane + i * 32) * NLD + l];
#pragma unroll
        for (int o = 16; o > 0; o >>= 1) acc += __shfl_down_sync(0xffffffffu, acc, o);
        if (lane == 0)
            pred[((size_t)b * NLD + l) * SEG + s] = acc + bd[l];
    }
}

// ---------------- host launcher ----------------
extern "C" void kernel_launch(void* const* d_in, const int* in_sizes, int n_in,
                              void* d_out, int out_size) {
    (void)in_sizes; (void)n_in; (void)out_size;
    const float* src      = (const float*)d_in[0];
    const float* mems     = (const float*)d_in[1];
    const unsigned char* mask = (const unsigned char*)d_in[2];
    const float* W_in     = (const float*)d_in[3];
    const float* b_in     = (const float*)d_in[4];
    const float* qkv_w    = (const float*)d_in[5];
    const float* r_net_w  = (const float*)d_in[6];
    const float* o_w      = (const float*)d_in[7];
    const float* ln1_g    = (const float*)d_in[8];
    const float* ln1_b    = (const float*)d_in[9];
    const float* ff_w1    = (const float*)d_in[10];
    const float* ff_b1    = (const float*)d_in[11];
    const float* ff_w2    = (const float*)d_in[12];
    const float* ff_b2    = (const float*)d_in[13];
    const float* ln2_g    = (const float*)d_in[14];
    const float* ln2_b    = (const float*)d_in[15];
    const float* W_dec    = (const float*)d_in[16];
    const float* b_dec    = (const float*)d_in[17];
    const float* r_w_bias = (const float*)d_in[18];
    const float* r_r_bias = (const float*)d_in[19];

    float* out    = (float*)d_out;
    float* pred   = out;
    float* memout = out + PRED_N;

    static __half *heads_p=nullptr, *rkh_p=nullptr, *rh_p=nullptr, *coreh_p=nullptr,
                  *midh_p=nullptr, *wqkv_p=nullptr, *wrnet_p=nullptr, *wo_p=nullptr,
                  *wff1_p=nullptr, *wff2_p=nullptr, *memsh_p=nullptr;
    static float *vec_p=nullptr;
    if (!heads_p) {
        cudaGetSymbolAddress((void**)&heads_p, g_heads_h);
        cudaGetSymbolAddress((void**)&rkh_p,   g_rk_h);
        cudaGetSymbolAddress((void**)&rh_p,    g_r_h);
        cudaGetSymbolAddress((void**)&coreh_p, g_core_h);
        cudaGetSymbolAddress((void**)&midh_p,  g_mid_h);
        cudaGetSymbolAddress((void**)&wqkv_p,  g_wqkv_h);
        cudaGetSymbolAddress((void**)&wrnet_p, g_wrnet_h);
        cudaGetSymbolAddress((void**)&wo_p,    g_wo_h);
        cudaGetSymbolAddress((void**)&wff1_p,  g_wff1_h);
        cudaGetSymbolAddress((void**)&wff2_p,  g_wff2_h);
        cudaGetSymbolAddress((void**)&memsh_p, g_mems_h);
        cudaGetSymbolAddress((void**)&vec_p,   g_vec);
    }

    // ---- prep: batched weight transpose, merged misc (mems cvt + pos), input proj ----
    k_transp_all<<<3328, dim3(32, 8)>>>(qkv_w, r_net_w, o_w, ff_w1, ff_w2);
    k_prep_misc<<<(CVT_T + POS_T + 255)/256, 256>>>(mems, memsh_p);
    k_input_proj<<<(CORE_N + 255)/256, 256>>>(src, W_in, b_in, memout);

    // rk for ALL layers, z-batched fp16 GEMM: rk_h[l] = r @ r_net_w[l]
    k_gemm_f16<64><<<dim3(DM/64, KL/64, LNUM), 256>>>(rh_p, 0, nullptr, wrnet_p,
                                                      nullptr, rkh_p, KL, DM, DM,
                                                      nullptr, 0, (size_t)DM*DM, (size_t)KL*DM);

    for (int i = 0; i < LNUM; i++) {
        // heads = [mems_h_i ; core_h] @ qkv_w[i]   [4096 x 768 x 256]
        k_gemm_f16<128><<<dim3(H3/64, (KL*BSZ)/128, 1), 256>>>(
            nullptr, 100, memsh_p + (size_t)i * MEML*BSZ*DM, wqkv_p + (size_t)i*H3*DM,
            nullptr, heads_p, KL*BSZ, H3, DM, nullptr, 0, 0, 0);
        // AC and BDpre in one launch (z = bh*2+mode), 128x128 tiles, fp16 mma
        k_qk_f16<<<dim3(KL/128, SEG/128, BSZ*NH*2), 256>>>(r_w_bias, r_r_bias,
                                                           rkh_p + (size_t)i*KL*DM);
        // shift + combine + mask + softmax (fp16 in place)
        k_softmax<<<dim3(SEG, BSZ*NH), 256>>>(mask);
        // PV split-K (fp16 partials; reduction folded into the o-proj GEMM A-load)
        k_pv_f16<<<dim3(SEG/64, BSZ*NH, 4), 128>>>();
        // attn output projection [2048 x 256 x 256], A = sum of PV partials -> g_vec fp32
        k_gemm_f16<64><<<dim3(DM/64, (SEG*BSZ)/64, 1), 256>>>(
            nullptr, 101, nullptr, wo_p + (size_t)i*DM*DM,
            vec_p, nullptr, SEG*BSZ, DM, DM, nullptr, 0, 0, 0);
        k_addln<<<SEG*BSZ, DM>>>(ln1_g + i*DM, ln1_b + i*DM, nullptr);
        // ff1 + bias + relu [2048 x 1024 x 256] -> mid_h fp16
        k_gemm_f16<128><<<dim3(DI/64, (SEG*BSZ)/128, 1), 256>>>(
            coreh_p, 0, nullptr, wff1_p + (size_t)i*DI*DM,
            nullptr, midh_p, SEG*BSZ, DI, DM, ff_b1 + i*DI, 1, 0, 0);
        // ff2 + bias [2048 x 256 x 1024] -> g_vec fp32
        k_gemm_f16<64><<<dim3(DM/64, (SEG*BSZ)/64, 1), 256>>>(
            midh_p, 0, nullptr, wff2_p + (size_t)i*DM*DI,
            vec_p, nullptr, SEG*BSZ, DM, DI, ff_b2 + i*DM, 0, 0, 0);
        k_addln<<<SEG*BSZ, DM>>>(ln2_g + i*DM, ln2_b + i*DM,
                                 memout + (size_t)(i+1)*CORE_N);
    }
    k_dec<<<(SEG*BSZ)/8, 256>>>(W_dec, b_dec, pred);
}